// round 9
// baseline (speedup 1.0000x reference)
#include <cuda_runtime.h>
#include <cuda_bf16.h>
#include <cuda_fp16.h>
#include <mma.h>
#include <cstdint>
#include <cstddef>
using namespace nvcuda;

#define B_  2048
#define T_  128
#define F_  64
#define H_  256
#define G3  768
#define OL  32
#define FCH 256

// ---- device scratch ----
__device__ float  g_h[2][B_ * H_];
__device__ float  g_gi[(size_t)B_ * T_ * G3];     // x@Wih^T precompute
__device__ __half g_hs[(size_t)B_ * T_ * H_];     // encoder outputs fp16
__device__ float  g_Asc[B_ * T_], g_Csc[B_ * T_];
__device__ float  g_ctx[B_ * H_], g_hd[B_ * H_];
__device__ float  g_prev0[B_], g_prev[B_];
__device__ __nv_bfloat16 ih_hi[G3 * F_], ih_lo[G3 * F_];
__device__ __nv_bfloat16 eh_hi[G3 * H_], eh_lo[G3 * H_];
__device__ __nv_bfloat16 dh_hi[G3 * H_], dh_lo[G3 * H_];
__device__ __nv_bfloat16 f1_hi[FCH * H_], f1_lo[FCH * H_];

__device__ __forceinline__ void split1(float w, __nv_bfloat16* hi, __nv_bfloat16* lo, int i) {
    __nv_bfloat16 h = __float2bfloat16(w);
    hi[i] = h;
    lo[i] = __float2bfloat16(w - __bfloat162float(h));
}
__device__ __forceinline__ float sigf(float v) { return 1.f / (1.f + expf(-v)); }

// ---- prep ----
__global__ void prep_weights(const float* __restrict__ eWih, const float* __restrict__ eWhh,
                             const float* __restrict__ dWhh, const float* __restrict__ f1W)
{
    int i = blockIdx.x * blockDim.x + threadIdx.x;
    const int n0 = G3 * F_, n1 = G3 * H_, n2 = G3 * H_, n3 = FCH * H_;
    if (i < n0) split1(eWih[i], ih_hi, ih_lo, i);
    else if (i < n0 + n1) split1(eWhh[i - n0], eh_hi, eh_lo, i - n0);
    else if (i < n0 + n1 + n2) split1(dWhh[i - n0 - n1], dh_hi, dh_lo, i - n0 - n1);
    else if (i < n0 + n1 + n2 + n3) split1(f1W[i - n0 - n1 - n2], f1_hi, f1_lo, i - n0 - n1 - n2);
}

__global__ void prep_state(const float* __restrict__ x, const float* __restrict__ h0)
{
    int i = blockIdx.x * blockDim.x + threadIdx.x;
    if (i < B_ * H_) g_h[0][i] = h0[i];
    if (i < B_)      g_prev0[i] = x[((size_t)i * T_ + (T_ - 1)) * F_ + 0];
}

// ---- generic GEMM (kept for gi precompute only): C=A@W^T, 3-product split ----
__global__ void __launch_bounds__(256) gemm_split(
    const float* __restrict__ A, int lda,
    const __nv_bfloat16* __restrict__ Wh, const __nv_bfloat16* __restrict__ Wl,
    float* __restrict__ C, int ldc, int K)
{
    __shared__ __align__(16) char smem[128 * 68 * 4];
    __nv_bfloat16* sAh = (__nv_bfloat16*)smem;
    __nv_bfloat16* sAl = sAh + 128 * 40;
    __nv_bfloat16* sBh = sAl + 128 * 40;
    __nv_bfloat16* sBl = sBh + 64 * 40;
    float* sC = (float*)smem;

    const int tid  = threadIdx.x;
    const int row0 = blockIdx.x * 128;
    const int ns   = blockIdx.y * 64;
    const int w    = tid >> 5;
    const int m0   = (w & 3) * 32, n0 = (w >> 2) * 32;

    wmma::fragment<wmma::accumulator, 16, 16, 16, float> acc[2][2];
    #pragma unroll
    for (int a = 0; a < 2; a++)
        #pragma unroll
        for (int b = 0; b < 2; b++) wmma::fill_fragment(acc[a][b], 0.f);

    for (int kc = 0; kc < K; kc += 32) {
        for (int idx = tid; idx < 128 * 32; idx += 256) {
            int m = idx >> 5, kk = idx & 31;
            float v = A[(size_t)(row0 + m) * lda + kc + kk];
            __nv_bfloat16 h = __float2bfloat16(v);
            sAh[m * 40 + kk] = h;
            sAl[m * 40 + kk] = __float2bfloat16(v - __bfloat162float(h));
        }
        for (int idx = tid; idx < 64 * 32; idx += 256) {
            int n = idx >> 5, kk = idx & 31;
            size_t gi = (size_t)(ns + n) * K + kc + kk;
            sBh[n * 40 + kk] = Wh[gi];
            sBl[n * 40 + kk] = Wl[gi];
        }
        __syncthreads();
        #pragma unroll
        for (int k16 = 0; k16 < 2; k16++) {
            wmma::fragment<wmma::matrix_a, 16, 16, 16, __nv_bfloat16, wmma::row_major> ah[2], al[2];
            #pragma unroll
            for (int mf = 0; mf < 2; mf++) {
                wmma::load_matrix_sync(ah[mf], sAh + (m0 + mf * 16) * 40 + k16 * 16, 40);
                wmma::load_matrix_sync(al[mf], sAl + (m0 + mf * 16) * 40 + k16 * 16, 40);
            }
            #pragma unroll
            for (int nf = 0; nf < 2; nf++) {
                wmma::fragment<wmma::matrix_b, 16, 16, 16, __nv_bfloat16, wmma::col_major> bh, bl;
                wmma::load_matrix_sync(bh, sBh + (n0 + nf * 16) * 40 + k16 * 16, 40);
                wmma::load_matrix_sync(bl, sBl + (n0 + nf * 16) * 40 + k16 * 16, 40);
                #pragma unroll
                for (int mf = 0; mf < 2; mf++) {
                    wmma::mma_sync(acc[mf][nf], ah[mf], bh, acc[mf][nf]);
                    wmma::mma_sync(acc[mf][nf], ah[mf], bl, acc[mf][nf]);
                    wmma::mma_sync(acc[mf][nf], al[mf], bh, acc[mf][nf]);
                }
            }
        }
        __syncthreads();
    }
    #pragma unroll
    for (int mf = 0; mf < 2; mf++)
        #pragma unroll
        for (int nf = 0; nf < 2; nf++)
            wmma::store_matrix_sync(sC + (m0 + mf * 16) * 68 + n0 + nf * 16,
                                    acc[mf][nf], 68, wmma::mem_row_major);
    __syncthreads();
    for (int idx = tid; idx < 128 * 64; idx += 256) {
        int m = idx >> 6, n = idx & 63;
        C[(size_t)(row0 + m) * ldc + ns + n] = sC[m * 68 + n];
    }
}

// ---- fused GRU step (encoder & decoder) ----
// grid (B/64, 16). block 128 (4 warps). Block (mb,ns): rows r0=mb*64, h-cols ks=ns*16.
// GEMM: C[64x48] = A[64x256] @ Wsel^T, Wsel rows {g*256+ks+j : g in 0..2, j in 0..15}.
// Epilogue (warp-local): GRU gates, writes Hout (+hs for encoder).
__global__ void __launch_bounds__(128) gru_step(
    const float* __restrict__ Ain,                 // g_h[pin] (enc) or g_ctx (dec)
    const __nv_bfloat16* __restrict__ Wh, const __nv_bfloat16* __restrict__ Wl,
    const float* __restrict__ bih, const float* __restrict__ bhh,
    const float* __restrict__ gi,                  // enc: g_gi ; dec: null
    int t,
    const float* __restrict__ xw,                  // dec: dWih ; enc: null
    const float* __restrict__ prevp,               // dec: prev ; enc: null
    float* __restrict__ Hout,
    __half* __restrict__ hsout,                    // enc: g_hs ; dec: null
    int mode)
{
    __shared__ __nv_bfloat16 sAh[64 * 72], sAl[64 * 72];
    __shared__ __nv_bfloat16 sWh[48 * 72], sWl[48 * 72];
    __shared__ float sC[64 * 56];

    const int tid  = threadIdx.x;
    const int lane = tid & 31;
    const int w    = tid >> 5;
    const int r0   = blockIdx.x * 64;
    const int ks   = blockIdx.y * 16;

    wmma::fragment<wmma::accumulator, 16, 16, 16, float> acc[3];
    #pragma unroll
    for (int q = 0; q < 3; q++) wmma::fill_fragment(acc[q], 0.f);

    for (int kc = 0; kc < 4; kc++) {               // K chunks of 64
        for (int idx = tid; idx < 64 * 64; idx += 128) {
            int m = idx >> 6, kk = idx & 63;
            float v = Ain[(size_t)(r0 + m) * H_ + kc * 64 + kk];
            __nv_bfloat16 h = __float2bfloat16(v);
            sAh[m * 72 + kk] = h;
            sAl[m * 72 + kk] = __float2bfloat16(v - __bfloat162float(h));
        }
        for (int idx = tid; idx < 48 * 64; idx += 128) {
            int lr = idx >> 6, kk = idx & 63;
            int grow = (lr >> 4) * H_ + ks + (lr & 15);
            size_t gidx = (size_t)grow * H_ + kc * 64 + kk;
            sWh[lr * 72 + kk] = Wh[gidx];
            sWl[lr * 72 + kk] = Wl[gidx];
        }
        __syncthreads();
        #pragma unroll
        for (int k16 = 0; k16 < 4; k16++) {
            wmma::fragment<wmma::matrix_a, 16, 16, 16, __nv_bfloat16, wmma::row_major> ah, al;
            wmma::load_matrix_sync(ah, sAh + (w * 16) * 72 + k16 * 16, 72);
            wmma::load_matrix_sync(al, sAl + (w * 16) * 72 + k16 * 16, 72);
            #pragma unroll
            for (int nf = 0; nf < 3; nf++) {
                wmma::fragment<wmma::matrix_b, 16, 16, 16, __nv_bfloat16, wmma::col_major> bh, bl;
                wmma::load_matrix_sync(bh, sWh + (nf * 16) * 72 + k16 * 16, 72);
                wmma::load_matrix_sync(bl, sWl + (nf * 16) * 72 + k16 * 16, 72);
                wmma::mma_sync(acc[nf], ah, bh, acc[nf]);
                wmma::mma_sync(acc[nf], ah, bl, acc[nf]);
                wmma::mma_sync(acc[nf], al, bh, acc[nf]);
            }
        }
        __syncthreads();
    }
    #pragma unroll
    for (int nf = 0; nf < 3; nf++)
        wmma::store_matrix_sync(sC + (w * 16) * 56 + nf * 16, acc[nf], 56, wmma::mem_row_major);
    // warp-local epilogue: warp w owns rows [w*16, w*16+16), cols ks..ks+16
    #pragma unroll
    for (int e = 0; e < 8; e++) {
        int id = e * 32 + lane;
        int row = id >> 4, col = id & 15;
        int b = r0 + w * 16 + row;
        int k = ks + col;
        float ghR = sC[(w * 16 + row) * 56 + col]      + bhh[k];
        float ghZ = sC[(w * 16 + row) * 56 + 16 + col] + bhh[H_ + k];
        float ghN = sC[(w * 16 + row) * 56 + 32 + col] + bhh[2 * H_ + k];
        float giR, giZ, giN;
        if (mode == 0) {
            const float* gp = gi + ((size_t)b * T_ + t) * G3;
            giR = gp[k]          + bih[k];
            giZ = gp[H_ + k]     + bih[H_ + k];
            giN = gp[2 * H_ + k] + bih[2 * H_ + k];
        } else {
            float pv = prevp[b];
            giR = pv * xw[k]          + bih[k];
            giZ = pv * xw[H_ + k]     + bih[H_ + k];
            giN = pv * xw[2 * H_ + k] + bih[2 * H_ + k];
        }
        float r = sigf(giR + ghR);
        float z = sigf(giZ + ghZ);
        float n = tanhf(giN + r * ghN);
        float hold = Ain[(size_t)b * H_ + k];
        float hn = (1.f - z) * n + z * hold;
        Hout[(size_t)b * H_ + k] = hn;
        if (mode == 0) hsout[((size_t)b * T_ + t) * H_ + k] = __float2half(hn);
    }
}

// ---- attention precompute ----
__global__ void attn_pre(const float* __restrict__ Wq, const float* __restrict__ bq)
{
    int warp = threadIdx.x >> 5, lane = threadIdx.x & 31;
    int row = blockIdx.x * 8 + warp;
    const __half* hp = g_hs + (size_t)row * H_;
    float sa = 0.f, sc = 0.f;
    #pragma unroll
    for (int h = lane; h < H_; h += 32) {
        float v = __half2float(hp[h]);
        sa += Wq[h] * v;
        sc += bq[h] * v;
    }
    #pragma unroll
    for (int o = 16; o > 0; o >>= 1) {
        sa += __shfl_down_sync(0xffffffffu, sa, o);
        sc += __shfl_down_sync(0xffffffffu, sc, o);
    }
    if (lane == 0) { g_Asc[row] = sa; g_Csc[row] = sc; }
}

// ---- decoder attention: softmax + ctx (one block per batch) ----
__global__ void __launch_bounds__(256) dec_attn(const float* __restrict__ prevsrc)
{
    __shared__ float ssc[128];
    __shared__ float sred[2];
    const int b = blockIdx.x, tid = threadIdx.x;
    float prev = prevsrc[b];

    if (tid < 128)
        ssc[tid] = (prev * g_Asc[b * T_ + tid] + g_Csc[b * T_ + tid]) * 0.0625f;
    __syncthreads();
    if (tid < 32) {
        float m = -1e30f;
        for (int i = tid; i < 128; i += 32) m = fmaxf(m, ssc[i]);
        #pragma unroll
        for (int o = 16; o > 0; o >>= 1) m = fmaxf(m, __shfl_down_sync(0xffffffffu, m, o));
        if (tid == 0) sred[0] = m;
    }
    __syncthreads();
    float mx = sred[0];
    if (tid < 128) ssc[tid] = expf(ssc[tid] - mx);
    __syncthreads();
    if (tid < 32) {
        float sum = 0.f;
        for (int i = tid; i < 128; i += 32) sum += ssc[i];
        #pragma unroll
        for (int o = 16; o > 0; o >>= 1) sum += __shfl_down_sync(0xffffffffu, sum, o);
        if (tid == 0) sred[1] = sum;
    }
    __syncthreads();
    float inv = 1.f / sred[1];
    const __half* hp = g_hs + (size_t)b * T_ * H_ + tid;
    float accv = 0.f;
    #pragma unroll 4
    for (int t2 = 0; t2 < T_; t2++)
        accv += ssc[t2] * __half2float(hp[(size_t)t2 * H_]);
    g_ctx[b * H_ + tid] = accv * inv;
}

// ---- fused fc1(relu)+fc2: out[:,s] and prev ----
// grid B/32 = 64 blocks, block 256 (8 warps). C = hd[32x256]@f1^T in 4 N-chunks of 64.
__global__ void __launch_bounds__(256) fc_fused(
    const float* __restrict__ hd,
    const __nv_bfloat16* __restrict__ Wh, const __nv_bfloat16* __restrict__ Wl,
    const float* __restrict__ f1b, const float* __restrict__ f2W,
    const float* __restrict__ f2b,
    float* __restrict__ dout, float* __restrict__ prevout, int s)
{
    __shared__ __nv_bfloat16 sAh[32 * 72], sAl[32 * 72];
    __shared__ __nv_bfloat16 sWh[64 * 72], sWl[64 * 72];
    __shared__ float sC[32 * 68];

    const int tid  = threadIdx.x;
    const int lane = tid & 31;
    const int w    = tid >> 5;
    const int wm   = w & 1, wn = w >> 1;          // warp tile: (wm*16, wn*16) in 32x64
    const int r0   = blockIdx.x * 32;

    float fsum[4] = {0.f, 0.f, 0.f, 0.f};        // warp w accumulates fc2 for rows w*4..+4

    for (int nc = 0; nc < 4; nc++) {
        wmma::fragment<wmma::accumulator, 16, 16, 16, float> acc;
        wmma::fill_fragment(acc, 0.f);
        for (int kc = 0; kc < 4; kc++) {
            for (int idx = tid; idx < 32 * 64; idx += 256) {
                int m = idx >> 6, kk = idx & 63;
                float v = hd[(size_t)(r0 + m) * H_ + kc * 64 + kk];
                __nv_bfloat16 h = __float2bfloat16(v);
                sAh[m * 72 + kk] = h;
                sAl[m * 72 + kk] = __float2bfloat16(v - __bfloat162float(h));
            }
            for (int idx = tid; idx < 64 * 64; idx += 256) {
                int n = idx >> 6, kk = idx & 63;
                size_t gidx = (size_t)(nc * 64 + n) * H_ + kc * 64 + kk;
                sWh[n * 72 + kk] = Wh[gidx];
                sWl[n * 72 + kk] = Wl[gidx];
            }
            __syncthreads();
            #pragma unroll
            for (int k16 = 0; k16 < 4; k16++) {
                wmma::fragment<wmma::matrix_a, 16, 16, 16, __nv_bfloat16, wmma::row_major> ah, al;
                wmma::load_matrix_sync(ah, sAh + (wm * 16) * 72 + k16 * 16, 72);
                wmma::load_matrix_sync(al, sAl + (wm * 16) * 72 + k16 * 16, 72);
                wmma::fragment<wmma::matrix_b, 16, 16, 16, __nv_bfloat16, wmma::col_major> bh, bl;
                wmma::load_matrix_sync(bh, sWh + (wn * 16) * 72 + k16 * 16, 72);
                wmma::load_matrix_sync(bl, sWl + (wn * 16) * 72 + k16 * 16, 72);
                wmma::mma_sync(acc, ah, bh, acc);
                wmma::mma_sync(acc, ah, bl, acc);
                wmma::mma_sync(acc, al, bh, acc);
            }
            __syncthreads();
        }
        wmma::store_matrix_sync(sC + (wm * 16) * 68 + wn * 16, acc, 68, wmma::mem_row_major);
        __syncthreads();
        // fc2 partial over this N chunk: warp w -> rows w*4..w*4+4
        #pragma unroll
        for (int rr = 0; rr < 4; rr++) {
            int row = w * 4 + rr;
            float a0 = fmaxf(sC[row * 68 + lane]      + f1b[nc * 64 + lane],      0.f) * f2W[nc * 64 + lane];
            float a1 = fmaxf(sC[row * 68 + 32 + lane] + f1b[nc * 64 + 32 + lane], 0.f) * f2W[nc * 64 + 32 + lane];
            float v = a0 + a1;
            #pragma unroll
            for (int o = 16; o > 0; o >>= 1) v += __shfl_down_sync(0xffffffffu, v, o);
            if (lane == 0) fsum[rr] += v;
        }
        __syncthreads();
    }
    if (lane == 0) {
        #pragma unroll
        for (int rr = 0; rr < 4; rr++) {
            int b = r0 + w * 4 + rr;
            float o = fsum[rr] + f2b[0];
            dout[(size_t)b * OL + s] = o;
            prevout[b] = o;
        }
    }
}

// ---- host launch ----
extern "C" void kernel_launch(void* const* d_in, const int* in_sizes, int n_in,
                              void* d_out, int out_size)
{
    const float* x    = (const float*)d_in[0];
    const float* h0   = (const float*)d_in[1];
    const float* eWih = (const float*)d_in[2];
    const float* eWhh = (const float*)d_in[3];
    const float* ebih = (const float*)d_in[4];
    const float* ebhh = (const float*)d_in[5];
    const float* dWih = (const float*)d_in[6];
    const float* dWhh = (const float*)d_in[7];
    const float* dbih = (const float*)d_in[8];
    const float* dbhh = (const float*)d_in[9];
    const float* Wq   = (const float*)d_in[10];
    const float* bq   = (const float*)d_in[11];
    const float* f1W  = (const float*)d_in[12];
    const float* f1b  = (const float*)d_in[13];
    const float* f2W  = (const float*)d_in[14];
    const float* f2b  = (const float*)d_in[15];
    float* out = (float*)d_out;

    void *p_gi, *p_h, *p_ctx, *p_hd, *p_hs, *p_prev0, *p_prev;
    void *p_ihh, *p_ihl, *p_ehh, *p_ehl, *p_dhh, *p_dhl, *p_f1h, *p_f1l;
    cudaGetSymbolAddress(&p_gi, g_gi);
    cudaGetSymbolAddress(&p_h, g_h);
    cudaGetSymbolAddress(&p_ctx, g_ctx);
    cudaGetSymbolAddress(&p_hd, g_hd);
    cudaGetSymbolAddress(&p_hs, g_hs);
    cudaGetSymbolAddress(&p_prev0, g_prev0);
    cudaGetSymbolAddress(&p_prev, g_prev);
    cudaGetSymbolAddress(&p_ihh, ih_hi); cudaGetSymbolAddress(&p_ihl, ih_lo);
    cudaGetSymbolAddress(&p_ehh, eh_hi); cudaGetSymbolAddress(&p_ehl, eh_lo);
    cudaGetSymbolAddress(&p_dhh, dh_hi); cudaGetSymbolAddress(&p_dhl, dh_lo);
    cudaGetSymbolAddress(&p_f1h, f1_hi); cudaGetSymbolAddress(&p_f1l, f1_lo);

    prep_weights<<<(G3 * F_ + 2 * G3 * H_ + FCH * H_ + 255) / 256, 256>>>(eWih, eWhh, dWhh, f1W);
    prep_state<<<(B_ * H_ + 255) / 256, 256>>>(x, h0);

    // gi = X @ Wih^T (X viewed as [B*T, F])
    gemm_split<<<dim3(B_ * T_ / 128, G3 / 64), 256>>>(
        x, F_, (__nv_bfloat16*)p_ihh, (__nv_bfloat16*)p_ihl,
        (float*)p_gi, G3, F_);

    // encoder recurrence: one fused kernel per step
    int pin = 0;
    for (int t = 0; t < T_; t++) {
        gru_step<<<dim3(B_ / 64, 16), 128>>>(
            (float*)p_h + (size_t)pin * B_ * H_,
            (__nv_bfloat16*)p_ehh, (__nv_bfloat16*)p_ehl,
            ebih, ebhh,
            (const float*)p_gi, t,
            nullptr, nullptr,
            (float*)p_h + (size_t)(pin ^ 1) * B_ * H_,
            (__half*)p_hs, 0);
        pin ^= 1;
    }

    attn_pre<<<B_ * T_ / 8, 256>>>(Wq, bq);

    // decoder: 32 steps of (attention+ctx) -> (gru) -> (fc1+fc2)
    for (int s = 0; s < OL; s++) {
        const float* prevsrc = (s == 0) ? (const float*)p_prev0 : (const float*)p_prev;
        dec_attn<<<B_, 256>>>(prevsrc);
        gru_step<<<dim3(B_ / 64, 16), 128>>>(
            (float*)p_ctx,
            (__nv_bfloat16*)p_dhh, (__nv_bfloat16*)p_dhl,
            dbih, dbhh,
            nullptr, 0,
            dWih, prevsrc,
            (float*)p_hd, nullptr, 1);
        fc_fused<<<B_ / 32, 256>>>(
            (float*)p_hd,
            (__nv_bfloat16*)p_f1h, (__nv_bfloat16*)p_f1l,
            f1b, f2W, f2b,
            out, (float*)p_prev, s);
    }
}

// round 10
// speedup vs baseline: 1.1835x; 1.1835x over previous
#include <cuda_runtime.h>
#include <cuda_bf16.h>
#include <cuda_fp16.h>
#include <mma.h>
#include <cstdint>
#include <cstddef>
using namespace nvcuda;

#define B_  2048
#define T_  128
#define F_  64
#define H_  256
#define G3  768
#define OL  32
#define FCH 256

#define GRU_SMEM 64512   // max(GEMM bufs 63KB, C tile 50KB)

// ---- device scratch ----
__device__ __nv_bfloat16 g_hhi[2][B_ * H_], g_hlo[2][B_ * H_];   // hidden, split
__device__ float  g_gi[(size_t)B_ * T_ * G3];                    // x@Wih^T precompute
__device__ __half g_hs[(size_t)B_ * T_ * H_];                    // encoder outputs fp16
__device__ float  g_Asc[B_ * T_], g_Csc[B_ * T_];
__device__ __nv_bfloat16 g_ctxh[B_ * H_], g_ctxl[B_ * H_];
__device__ __nv_bfloat16 g_hdh[B_ * H_],  g_hdl[B_ * H_];
__device__ float  g_prev0[B_], g_prev[B_];
__device__ __nv_bfloat16 ih_hi[G3 * F_], ih_lo[G3 * F_];         // enc Wih (normal layout)
__device__ __nv_bfloat16 eh_hi[G3 * H_], eh_lo[G3 * H_];         // enc Whh gate-interleaved
__device__ __nv_bfloat16 dh_hi[G3 * H_], dh_lo[G3 * H_];         // dec Whh gate-interleaved
__device__ __nv_bfloat16 f1_hi[FCH * H_], f1_lo[FCH * H_];

__device__ __forceinline__ void split1(float w, __nv_bfloat16* hi, __nv_bfloat16* lo, size_t i) {
    __nv_bfloat16 h = __float2bfloat16(w);
    hi[i] = h;
    lo[i] = __float2bfloat16(w - __bfloat162float(h));
}
__device__ __forceinline__ float sigf(float v) { return 1.f / (1.f + expf(-v)); }

// ---- prep: split weights; reorder recurrent W rows to (k*3+g) ----
__global__ void prep_weights(const float* __restrict__ eWih, const float* __restrict__ eWhh,
                             const float* __restrict__ dWhh, const float* __restrict__ f1W)
{
    int i = blockIdx.x * blockDim.x + threadIdx.x;
    const int n0 = G3 * F_, n1 = G3 * H_, n2 = G3 * H_, n3 = FCH * H_;
    if (i < n0) {
        split1(eWih[i], ih_hi, ih_lo, i);
    } else if (i < n0 + n1) {
        int j = i - n0;
        int row = j / H_, col = j % H_;
        int g = row >> 8, k = row & 255;
        split1(eWhh[j], eh_hi, eh_lo, (size_t)(k * 3 + g) * H_ + col);
    } else if (i < n0 + n1 + n2) {
        int j = i - n0 - n1;
        int row = j / H_, col = j % H_;
        int g = row >> 8, k = row & 255;
        split1(dWhh[j], dh_hi, dh_lo, (size_t)(k * 3 + g) * H_ + col);
    } else if (i < n0 + n1 + n2 + n3) {
        split1(f1W[i - n0 - n1 - n2], f1_hi, f1_lo, i - n0 - n1 - n2);
    }
}

__global__ void prep_state(const float* __restrict__ x, const float* __restrict__ h0)
{
    int i = blockIdx.x * blockDim.x + threadIdx.x;
    if (i < B_ * H_) split1(h0[i], g_hhi[0], g_hlo[0], i);
    if (i < B_)      g_prev0[i] = x[((size_t)i * T_ + (T_ - 1)) * F_ + 0];
}

// ---- generic GEMM for gi precompute (fp32 A input): C=A@W^T, 3-product split ----
__global__ void __launch_bounds__(256) gemm_split(
    const float* __restrict__ A, int lda,
    const __nv_bfloat16* __restrict__ Wh, const __nv_bfloat16* __restrict__ Wl,
    float* __restrict__ C, int ldc, int K)
{
    __shared__ __align__(16) char smem[128 * 68 * 4];
    __nv_bfloat16* sAh = (__nv_bfloat16*)smem;
    __nv_bfloat16* sAl = sAh + 128 * 40;
    __nv_bfloat16* sBh = sAl + 128 * 40;
    __nv_bfloat16* sBl = sBh + 64 * 40;
    float* sC = (float*)smem;

    const int tid  = threadIdx.x;
    const int row0 = blockIdx.x * 128;
    const int ns   = blockIdx.y * 64;
    const int w    = tid >> 5;
    const int m0   = (w & 3) * 32, n0 = (w >> 2) * 32;

    wmma::fragment<wmma::accumulator, 16, 16, 16, float> acc[2][2];
    #pragma unroll
    for (int a = 0; a < 2; a++)
        #pragma unroll
        for (int b = 0; b < 2; b++) wmma::fill_fragment(acc[a][b], 0.f);

    for (int kc = 0; kc < K; kc += 32) {
        for (int idx = tid; idx < 128 * 32; idx += 256) {
            int m = idx >> 5, kk = idx & 31;
            float v = A[(size_t)(row0 + m) * lda + kc + kk];
            __nv_bfloat16 h = __float2bfloat16(v);
            sAh[m * 40 + kk] = h;
            sAl[m * 40 + kk] = __float2bfloat16(v - __bfloat162float(h));
        }
        for (int idx = tid; idx < 64 * 32; idx += 256) {
            int n = idx >> 5, kk = idx & 31;
            size_t gi = (size_t)(ns + n) * K + kc + kk;
            sBh[n * 40 + kk] = Wh[gi];
            sBl[n * 40 + kk] = Wl[gi];
        }
        __syncthreads();
        #pragma unroll
        for (int k16 = 0; k16 < 2; k16++) {
            wmma::fragment<wmma::matrix_a, 16, 16, 16, __nv_bfloat16, wmma::row_major> ah[2], al[2];
            #pragma unroll
            for (int mf = 0; mf < 2; mf++) {
                wmma::load_matrix_sync(ah[mf], sAh + (m0 + mf * 16) * 40 + k16 * 16, 40);
                wmma::load_matrix_sync(al[mf], sAl + (m0 + mf * 16) * 40 + k16 * 16, 40);
            }
            #pragma unroll
            for (int nf = 0; nf < 2; nf++) {
                wmma::fragment<wmma::matrix_b, 16, 16, 16, __nv_bfloat16, wmma::col_major> bh, bl;
                wmma::load_matrix_sync(bh, sBh + (n0 + nf * 16) * 40 + k16 * 16, 40);
                wmma::load_matrix_sync(bl, sBl + (n0 + nf * 16) * 40 + k16 * 16, 40);
                #pragma unroll
                for (int mf = 0; mf < 2; mf++) {
                    wmma::mma_sync(acc[mf][nf], ah[mf], bh, acc[mf][nf]);
                    wmma::mma_sync(acc[mf][nf], ah[mf], bl, acc[mf][nf]);
                    wmma::mma_sync(acc[mf][nf], al[mf], bh, acc[mf][nf]);
                }
            }
        }
        __syncthreads();
    }
    #pragma unroll
    for (int mf = 0; mf < 2; mf++)
        #pragma unroll
        for (int nf = 0; nf < 2; nf++)
            wmma::store_matrix_sync(sC + (m0 + mf * 16) * 68 + n0 + nf * 16,
                                    acc[mf][nf], 68, wmma::mem_row_major);
    __syncthreads();
    for (int idx = tid; idx < 128 * 64; idx += 256) {
        int m = idx >> 6, n = idx & 63;
        C[(size_t)(row0 + m) * ldc + ns + n] = sC[m * 68 + n];
    }
}

// ---- fused GRU step (encoder & decoder), pre-split inputs ----
// grid (B/128=16, H/32=8), block 256 (8 warps: 4 m-warps x 2 n-warps).
// Block: C[128x96] = A[128x256] @ Wint[96x256]^T, Wint rows = gate-interleaved (k*3+g)
// starting at ks*3. Epilogue: GRU gates, writes split Hout (+hs fp16 for encoder).
__global__ void __launch_bounds__(256) gru_step(
    const __nv_bfloat16* __restrict__ Ah, const __nv_bfloat16* __restrict__ Al,
    const __nv_bfloat16* __restrict__ Wh, const __nv_bfloat16* __restrict__ Wl,
    const float* __restrict__ bih, const float* __restrict__ bhh,
    const float* __restrict__ gi, int t,
    const float* __restrict__ xw, const float* __restrict__ prevp,
    __nv_bfloat16* __restrict__ Oh, __nv_bfloat16* __restrict__ Ol,
    __half* __restrict__ hsout, int mode)
{
    extern __shared__ __align__(16) char smem[];
    __nv_bfloat16* sAh = (__nv_bfloat16*)smem;             // 128 x 72
    __nv_bfloat16* sAl = sAh + 128 * 72;
    __nv_bfloat16* sWh = sAl + 128 * 72;                   // 96 x 72
    __nv_bfloat16* sWl = sWh + 96 * 72;
    float* sC = (float*)smem;                              // 128 x 100 (reused)

    const int tid  = threadIdx.x;
    const int w    = tid >> 5;
    const int m0   = (w & 3) * 32;
    const int n0   = (w >> 2) * 48;
    const int r0   = blockIdx.x * 128;
    const int ks   = blockIdx.y * 32;
    const int wr0  = ks * 3;

    wmma::fragment<wmma::accumulator, 16, 16, 16, float> acc[2][3];
    #pragma unroll
    for (int a = 0; a < 2; a++)
        #pragma unroll
        for (int b = 0; b < 3; b++) wmma::fill_fragment(acc[a][b], 0.f);

    for (int kc = 0; kc < 4; kc++) {                       // K chunks of 64
        // A tiles: vectorized copies (8 bf16 per uint4), no conversion
        for (int idx = tid; idx < 128 * 8; idx += 256) {
            int m = idx >> 3, v = idx & 7;
            size_t go = (size_t)(r0 + m) * H_ + kc * 64 + v * 8;
            *(uint4*)(sAh + m * 72 + v * 8) = *(const uint4*)(Ah + go);
            *(uint4*)(sAl + m * 72 + v * 8) = *(const uint4*)(Al + go);
        }
        for (int idx = tid; idx < 96 * 8; idx += 256) {
            int lr = idx >> 3, v = idx & 7;
            size_t go = (size_t)(wr0 + lr) * H_ + kc * 64 + v * 8;
            *(uint4*)(sWh + lr * 72 + v * 8) = *(const uint4*)(Wh + go);
            *(uint4*)(sWl + lr * 72 + v * 8) = *(const uint4*)(Wl + go);
        }
        __syncthreads();
        #pragma unroll
        for (int k16 = 0; k16 < 4; k16++) {
            wmma::fragment<wmma::matrix_a, 16, 16, 16, __nv_bfloat16, wmma::row_major> ah[2], al[2];
            #pragma unroll
            for (int mf = 0; mf < 2; mf++) {
                wmma::load_matrix_sync(ah[mf], sAh + (m0 + mf * 16) * 72 + k16 * 16, 72);
                wmma::load_matrix_sync(al[mf], sAl + (m0 + mf * 16) * 72 + k16 * 16, 72);
            }
            #pragma unroll
            for (int nf = 0; nf < 3; nf++) {
                wmma::fragment<wmma::matrix_b, 16, 16, 16, __nv_bfloat16, wmma::col_major> bh, bl;
                wmma::load_matrix_sync(bh, sWh + (n0 + nf * 16) * 72 + k16 * 16, 72);
                wmma::load_matrix_sync(bl, sWl + (n0 + nf * 16) * 72 + k16 * 16, 72);
                #pragma unroll
                for (int mf = 0; mf < 2; mf++) {
                    wmma::mma_sync(acc[mf][nf], ah[mf], bh, acc[mf][nf]);
                    wmma::mma_sync(acc[mf][nf], ah[mf], bl, acc[mf][nf]);
                    wmma::mma_sync(acc[mf][nf], al[mf], bh, acc[mf][nf]);
                }
            }
        }
        __syncthreads();
    }
    #pragma unroll
    for (int mf = 0; mf < 2; mf++)
        #pragma unroll
        for (int nf = 0; nf < 3; nf++)
            wmma::store_matrix_sync(sC + (m0 + mf * 16) * 100 + n0 + nf * 16,
                                    acc[mf][nf], 100, wmma::mem_row_major);
    __syncthreads();

    // epilogue: 128 rows x 32 hidden cols = 4096 elems, 16 per thread
    #pragma unroll
    for (int e = 0; e < 16; e++) {
        int id = e * 256 + tid;
        int m = id >> 5, kl = id & 31;
        int b = r0 + m;
        int k = ks + kl;
        float ghR = sC[m * 100 + kl * 3 + 0] + bhh[k];
        float ghZ = sC[m * 100 + kl * 3 + 1] + bhh[H_ + k];
        float ghN = sC[m * 100 + kl * 3 + 2] + bhh[2 * H_ + k];
        float giR, giZ, giN;
        if (mode == 0) {
            const float* gp = gi + ((size_t)b * T_ + t) * G3;
            giR = gp[k]          + bih[k];
            giZ = gp[H_ + k]     + bih[H_ + k];
            giN = gp[2 * H_ + k] + bih[2 * H_ + k];
        } else {
            float pv = prevp[b];
            giR = pv * xw[k]          + bih[k];
            giZ = pv * xw[H_ + k]     + bih[H_ + k];
            giN = pv * xw[2 * H_ + k] + bih[2 * H_ + k];
        }
        float r = sigf(giR + ghR);
        float z = sigf(giZ + ghZ);
        float n = tanhf(giN + r * ghN);
        size_t hi = (size_t)b * H_ + k;
        float hold = __bfloat162float(Ah[hi]) + __bfloat162float(Al[hi]);
        float hn = (1.f - z) * n + z * hold;
        __nv_bfloat16 bh_ = __float2bfloat16(hn);
        Oh[hi] = bh_;
        Ol[hi] = __float2bfloat16(hn - __bfloat162float(bh_));
        if (mode == 0) hsout[((size_t)b * T_ + t) * H_ + k] = __float2half(hn);
    }
}

// ---- attention precompute: Asc = Wq.hs, Csc = bq.hs ----
__global__ void attn_pre(const float* __restrict__ Wq, const float* __restrict__ bq)
{
    int warp = threadIdx.x >> 5, lane = threadIdx.x & 31;
    int row = blockIdx.x * 8 + warp;
    const __half* hp = g_hs + (size_t)row * H_;
    float sa = 0.f, sc = 0.f;
    #pragma unroll
    for (int h = lane; h < H_; h += 32) {
        float v = __half2float(hp[h]);
        sa += Wq[h] * v;
        sc += bq[h] * v;
    }
    #pragma unroll
    for (int o = 16; o > 0; o >>= 1) {
        sa += __shfl_down_sync(0xffffffffu, sa, o);
        sc += __shfl_down_sync(0xffffffffu, sc, o);
    }
    if (lane == 0) { g_Asc[row] = sa; g_Csc[row] = sc; }
}

// ---- decoder attention: softmax + ctx (split output). one block per batch ----
__global__ void __launch_bounds__(256) dec_attn(const float* __restrict__ prevsrc)
{
    __shared__ float ssc[128];
    __shared__ float sred[2];
    const int b = blockIdx.x, tid = threadIdx.x;
    float prev = prevsrc[b];

    if (tid < 128)
        ssc[tid] = (prev * g_Asc[b * T_ + tid] + g_Csc[b * T_ + tid]) * 0.0625f;
    __syncthreads();
    if (tid < 32) {
        float m = -1e30f;
        for (int i = tid; i < 128; i += 32) m = fmaxf(m, ssc[i]);
        #pragma unroll
        for (int o = 16; o > 0; o >>= 1) m = fmaxf(m, __shfl_down_sync(0xffffffffu, m, o));
        if (tid == 0) sred[0] = m;
    }
    __syncthreads();
    float mx = sred[0];
    if (tid < 128) ssc[tid] = expf(ssc[tid] - mx);
    __syncthreads();
    if (tid < 32) {
        float sum = 0.f;
        for (int i = tid; i < 128; i += 32) sum += ssc[i];
        #pragma unroll
        for (int o = 16; o > 0; o >>= 1) sum += __shfl_down_sync(0xffffffffu, sum, o);
        if (tid == 0) sred[1] = sum;
    }
    __syncthreads();
    float inv = 1.f / sred[1];
    const __half* hp = g_hs + (size_t)b * T_ * H_ + tid;
    float accv = 0.f;
    #pragma unroll 4
    for (int t2 = 0; t2 < T_; t2++)
        accv += ssc[t2] * __half2float(hp[(size_t)t2 * H_]);
    float v = accv * inv;
    __nv_bfloat16 h = __float2bfloat16(v);
    g_ctxh[b * H_ + tid] = h;
    g_ctxl[b * H_ + tid] = __float2bfloat16(v - __bfloat162float(h));
}

// ---- fused fc1(relu)+fc2: out[:,s] and prev. hd pre-split input ----
__global__ void __launch_bounds__(256) fc_fused(
    const __nv_bfloat16* __restrict__ Wh, const __nv_bfloat16* __restrict__ Wl,
    const float* __restrict__ f1b, const float* __restrict__ f2W,
    const float* __restrict__ f2b,
    float* __restrict__ dout, float* __restrict__ prevout, int s)
{
    __shared__ __align__(16) __nv_bfloat16 sAh[32 * 72], sAl[32 * 72];
    __shared__ __align__(16) __nv_bfloat16 sWh[64 * 72], sWl[64 * 72];
    __shared__ float sC[32 * 68];

    const int tid  = threadIdx.x;
    const int lane = tid & 31;
    const int w    = tid >> 5;
    const int wm   = w & 1, wn = w >> 1;
    const int r0   = blockIdx.x * 32;

    float fsum[4] = {0.f, 0.f, 0.f, 0.f};

    for (int nc = 0; nc < 4; nc++) {
        wmma::fragment<wmma::accumulator, 16, 16, 16, float> acc;
        wmma::fill_fragment(acc, 0.f);
        for (int kc = 0; kc < 4; kc++) {
            for (int idx = tid; idx < 32 * 8; idx += 256) {
                int m = idx >> 3, v = idx & 7;
                size_t go = (size_t)(r0 + m) * H_ + kc * 64 + v * 8;
                *(uint4*)(sAh + m * 72 + v * 8) = *(const uint4*)(g_hdh + go);
                *(uint4*)(sAl + m * 72 + v * 8) = *(const uint4*)(g_hdl + go);
            }
            for (int idx = tid; idx < 64 * 8; idx += 256) {
                int n = idx >> 3, v = idx & 7;
                size_t go = (size_t)(nc * 64 + n) * H_ + kc * 64 + v * 8;
                *(uint4*)(sWh + n * 72 + v * 8) = *(const uint4*)(Wh + go);
                *(uint4*)(sWl + n * 72 + v * 8) = *(const uint4*)(Wl + go);
            }
            __syncthreads();
            #pragma unroll
            for (int k16 = 0; k16 < 4; k16++) {
                wmma::fragment<wmma::matrix_a, 16, 16, 16, __nv_bfloat16, wmma::row_major> ah, al;
                wmma::load_matrix_sync(ah, sAh + (wm * 16) * 72 + k16 * 16, 72);
                wmma::load_matrix_sync(al, sAl + (wm * 16) * 72 + k16 * 16, 72);
                wmma::fragment<wmma::matrix_b, 16, 16, 16, __nv_bfloat16, wmma::col_major> bh, bl;
                wmma::load_matrix_sync(bh, sWh + (wn * 16) * 72 + k16 * 16, 72);
                wmma::load_matrix_sync(bl, sWl + (wn * 16) * 72 + k16 * 16, 72);
                wmma::mma_sync(acc, ah, bh, acc);
                wmma::mma_sync(acc, ah, bl, acc);
                wmma::mma_sync(acc, al, bh, acc);
            }
            __syncthreads();
        }
        wmma::store_matrix_sync(sC + (wm * 16) * 68 + wn * 16, acc, 68, wmma::mem_row_major);
        __syncthreads();
        #pragma unroll
        for (int rr = 0; rr < 4; rr++) {
            int row = w * 4 + rr;
            float a0 = fmaxf(sC[row * 68 + lane]      + f1b[nc * 64 + lane],      0.f) * f2W[nc * 64 + lane];
            float a1 = fmaxf(sC[row * 68 + 32 + lane] + f1b[nc * 64 + 32 + lane], 0.f) * f2W[nc * 64 + 32 + lane];
            float v = a0 + a1;
            #pragma unroll
            for (int o = 16; o > 0; o >>= 1) v += __shfl_down_sync(0xffffffffu, v, o);
            if (lane == 0) fsum[rr] += v;
        }
        __syncthreads();
    }
    if (lane == 0) {
        #pragma unroll
        for (int rr = 0; rr < 4; rr++) {
            int b = r0 + w * 4 + rr;
            float o = fsum[rr] + f2b[0];
            dout[(size_t)b * OL + s] = o;
            prevout[b] = o;
        }
    }
}

// ---- host launch ----
extern "C" void kernel_launch(void* const* d_in, const int* in_sizes, int n_in,
                              void* d_out, int out_size)
{
    const float* x    = (const float*)d_in[0];
    const float* h0   = (const float*)d_in[1];
    const float* eWih = (const float*)d_in[2];
    const float* eWhh = (const float*)d_in[3];
    const float* ebih = (const float*)d_in[4];
    const float* ebhh = (const float*)d_in[5];
    const float* dWih = (const float*)d_in[6];
    const float* dWhh = (const float*)d_in[7];
    const float* dbih = (const float*)d_in[8];
    const float* dbhh = (const float*)d_in[9];
    const float* Wq   = (const float*)d_in[10];
    const float* bq   = (const float*)d_in[11];
    const float* f1W  = (const float*)d_in[12];
    const float* f1b  = (const float*)d_in[13];
    const float* f2W  = (const float*)d_in[14];
    const float* f2b  = (const float*)d_in[15];
    float* out = (float*)d_out;

    cudaFuncSetAttribute(gru_step, cudaFuncAttributeMaxDynamicSharedMemorySize, GRU_SMEM);

    void *p_gi, *p_hhi, *p_hlo, *p_ctxh, *p_ctxl, *p_hdh, *p_hdl, *p_hs, *p_prev0, *p_prev;
    void *p_ihh, *p_ihl, *p_ehh, *p_ehl, *p_dhh, *p_dhl, *p_f1h, *p_f1l;
    cudaGetSymbolAddress(&p_gi, g_gi);
    cudaGetSymbolAddress(&p_hhi, g_hhi);
    cudaGetSymbolAddress(&p_hlo, g_hlo);
    cudaGetSymbolAddress(&p_ctxh, g_ctxh);
    cudaGetSymbolAddress(&p_ctxl, g_ctxl);
    cudaGetSymbolAddress(&p_hdh, g_hdh);
    cudaGetSymbolAddress(&p_hdl, g_hdl);
    cudaGetSymbolAddress(&p_hs, g_hs);
    cudaGetSymbolAddress(&p_prev0, g_prev0);
    cudaGetSymbolAddress(&p_prev, g_prev);
    cudaGetSymbolAddress(&p_ihh, ih_hi); cudaGetSymbolAddress(&p_ihl, ih_lo);
    cudaGetSymbolAddress(&p_ehh, eh_hi); cudaGetSymbolAddress(&p_ehl, eh_lo);
    cudaGetSymbolAddress(&p_dhh, dh_hi); cudaGetSymbolAddress(&p_dhl, dh_lo);
    cudaGetSymbolAddress(&p_f1h, f1_hi); cudaGetSymbolAddress(&p_f1l, f1_lo);

    prep_weights<<<(G3 * F_ + 2 * G3 * H_ + FCH * H_ + 255) / 256, 256>>>(eWih, eWhh, dWhh, f1W);
    prep_state<<<(B_ * H_ + 255) / 256, 256>>>(x, h0);

    // gi = X @ Wih^T (X viewed as [B*T, F])
    gemm_split<<<dim3(B_ * T_ / 128, G3 / 64), 256>>>(
        x, F_, (__nv_bfloat16*)p_ihh, (__nv_bfloat16*)p_ihl,
        (float*)p_gi, G3, F_);

    // encoder recurrence
    int pin = 0;
    for (int t = 0; t < T_; t++) {
        gru_step<<<dim3(B_ / 128, H_ / 32), 256, GRU_SMEM>>>(
            (__nv_bfloat16*)p_hhi + (size_t)pin * B_ * H_,
            (__nv_bfloat16*)p_hlo + (size_t)pin * B_ * H_,
            (__nv_bfloat16*)p_ehh, (__nv_bfloat16*)p_ehl,
            ebih, ebhh,
            (const float*)p_gi, t,
            nullptr, nullptr,
            (__nv_bfloat16*)p_hhi + (size_t)(pin ^ 1) * B_ * H_,
            (__nv_bfloat16*)p_hlo + (size_t)(pin ^ 1) * B_ * H_,
            (__half*)p_hs, 0);
        pin ^= 1;
    }

    attn_pre<<<B_ * T_ / 8, 256>>>(Wq, bq);

    // decoder: 32 steps of (attention+ctx) -> (gru) -> (fc1+fc2)
    for (int s = 0; s < OL; s++) {
        const float* prevsrc = (s == 0) ? (const float*)p_prev0 : (const float*)p_prev;
        dec_attn<<<B_, 256>>>(prevsrc);
        gru_step<<<dim3(B_ / 128, H_ / 32), 256, GRU_SMEM>>>(
            (__nv_bfloat16*)p_ctxh, (__nv_bfloat16*)p_ctxl,
            (__nv_bfloat16*)p_dhh, (__nv_bfloat16*)p_dhl,
            dbih, dbhh,
            nullptr, 0,
            dWih, prevsrc,
            (__nv_bfloat16*)p_hdh, (__nv_bfloat16*)p_hdl,
            nullptr, 1);
        fc_fused<<<B_ / 32, 256>>>(
            (__nv_bfloat16*)p_f1h, (__nv_bfloat16*)p_f1l,
            f1b, f2W, f2b,
            out, (float*)p_prev, s);
    }
}

// round 11
// speedup vs baseline: 1.3833x; 1.1688x over previous
#include <cuda_runtime.h>
#include <cuda_bf16.h>
#include <cuda_fp16.h>
#include <mma.h>
#include <cstdint>
#include <cstddef>
using namespace nvcuda;

#define B_  2048
#define T_  128
#define F_  64
#define H_  256
#define G3  768
#define OL  32
#define FCH 256

// gru_step smem: 2 stages x (A 64x72 hi/lo + W 96x72 hi/lo) bf16
#define STAGE_BYTES (2 * (64 * 72 + 96 * 72) * 2)
#define GRU_SMEM    (2 * STAGE_BYTES)            // 92160 B

// ---- device scratch ----
__device__ __nv_bfloat16 g_hhi[2][B_ * H_], g_hlo[2][B_ * H_];   // hidden, split
__device__ float  g_gi[(size_t)B_ * T_ * G3];                    // x@Wih^T precompute
__device__ __half g_hs[(size_t)B_ * T_ * H_];                    // encoder outputs fp16
__device__ float  g_Asc[B_ * T_], g_Csc[B_ * T_];
__device__ __nv_bfloat16 g_ctxh[B_ * H_], g_ctxl[B_ * H_];
__device__ __nv_bfloat16 g_hdh[B_ * H_],  g_hdl[B_ * H_];
__device__ float  g_prev0[B_], g_prev[B_];
__device__ __nv_bfloat16 ih_hi[G3 * F_], ih_lo[G3 * F_];         // enc Wih
__device__ __nv_bfloat16 eh_hi[G3 * H_], eh_lo[G3 * H_];         // enc Whh gate-interleaved
__device__ __nv_bfloat16 dh_hi[G3 * H_], dh_lo[G3 * H_];         // dec Whh gate-interleaved
__device__ __nv_bfloat16 f1_hi[FCH * H_], f1_lo[FCH * H_];

__device__ __forceinline__ void split1(float w, __nv_bfloat16* hi, __nv_bfloat16* lo, size_t i) {
    __nv_bfloat16 h = __float2bfloat16(w);
    hi[i] = h;
    lo[i] = __float2bfloat16(w - __bfloat162float(h));
}
__device__ __forceinline__ float sigf(float v) { return 1.f / (1.f + expf(-v)); }

__device__ __forceinline__ void cpa16(void* s, const void* g) {
    uint32_t sa = (uint32_t)__cvta_generic_to_shared(s);
    asm volatile("cp.async.cg.shared.global [%0], [%1], 16;\n" :: "r"(sa), "l"(g));
}

// ---- prep: split weights; reorder recurrent W rows to (k*3+g) ----
__global__ void prep_weights(const float* __restrict__ eWih, const float* __restrict__ eWhh,
                             const float* __restrict__ dWhh, const float* __restrict__ f1W)
{
    int i = blockIdx.x * blockDim.x + threadIdx.x;
    const int n0 = G3 * F_, n1 = G3 * H_, n2 = G3 * H_, n3 = FCH * H_;
    if (i < n0) {
        split1(eWih[i], ih_hi, ih_lo, i);
    } else if (i < n0 + n1) {
        int j = i - n0;
        int row = j / H_, col = j % H_;
        int g = row >> 8, k = row & 255;
        split1(eWhh[j], eh_hi, eh_lo, (size_t)(k * 3 + g) * H_ + col);
    } else if (i < n0 + n1 + n2) {
        int j = i - n0 - n1;
        int row = j / H_, col = j % H_;
        int g = row >> 8, k = row & 255;
        split1(dWhh[j], dh_hi, dh_lo, (size_t)(k * 3 + g) * H_ + col);
    } else if (i < n0 + n1 + n2 + n3) {
        split1(f1W[i - n0 - n1 - n2], f1_hi, f1_lo, i - n0 - n1 - n2);
    }
}

__global__ void prep_state(const float* __restrict__ x, const float* __restrict__ h0)
{
    int i = blockIdx.x * blockDim.x + threadIdx.x;
    if (i < B_ * H_) split1(h0[i], g_hhi[0], g_hlo[0], i);
    if (i < B_)      g_prev0[i] = x[((size_t)i * T_ + (T_ - 1)) * F_ + 0];
}

// ---- generic GEMM for gi precompute (fp32 A input): C=A@W^T, 3-product split ----
__global__ void __launch_bounds__(256) gemm_split(
    const float* __restrict__ A, int lda,
    const __nv_bfloat16* __restrict__ Wh, const __nv_bfloat16* __restrict__ Wl,
    float* __restrict__ C, int ldc, int K)
{
    __shared__ __align__(16) char smem[128 * 68 * 4];
    __nv_bfloat16* sAh = (__nv_bfloat16*)smem;
    __nv_bfloat16* sAl = sAh + 128 * 40;
    __nv_bfloat16* sBh = sAl + 128 * 40;
    __nv_bfloat16* sBl = sBh + 64 * 40;
    float* sC = (float*)smem;

    const int tid  = threadIdx.x;
    const int row0 = blockIdx.x * 128;
    const int ns   = blockIdx.y * 64;
    const int w    = tid >> 5;
    const int m0   = (w & 3) * 32, n0 = (w >> 2) * 32;

    wmma::fragment<wmma::accumulator, 16, 16, 16, float> acc[2][2];
    #pragma unroll
    for (int a = 0; a < 2; a++)
        #pragma unroll
        for (int b = 0; b < 2; b++) wmma::fill_fragment(acc[a][b], 0.f);

    for (int kc = 0; kc < K; kc += 32) {
        for (int idx = tid; idx < 128 * 32; idx += 256) {
            int m = idx >> 5, kk = idx & 31;
            float v = A[(size_t)(row0 + m) * lda + kc + kk];
            __nv_bfloat16 h = __float2bfloat16(v);
            sAh[m * 40 + kk] = h;
            sAl[m * 40 + kk] = __float2bfloat16(v - __bfloat162float(h));
        }
        for (int idx = tid; idx < 64 * 32; idx += 256) {
            int n = idx >> 5, kk = idx & 31;
            size_t gi = (size_t)(ns + n) * K + kc + kk;
            sBh[n * 40 + kk] = Wh[gi];
            sBl[n * 40 + kk] = Wl[gi];
        }
        __syncthreads();
        #pragma unroll
        for (int k16 = 0; k16 < 2; k16++) {
            wmma::fragment<wmma::matrix_a, 16, 16, 16, __nv_bfloat16, wmma::row_major> ah[2], al[2];
            #pragma unroll
            for (int mf = 0; mf < 2; mf++) {
                wmma::load_matrix_sync(ah[mf], sAh + (m0 + mf * 16) * 40 + k16 * 16, 40);
                wmma::load_matrix_sync(al[mf], sAl + (m0 + mf * 16) * 40 + k16 * 16, 40);
            }
            #pragma unroll
            for (int nf = 0; nf < 2; nf++) {
                wmma::fragment<wmma::matrix_b, 16, 16, 16, __nv_bfloat16, wmma::col_major> bh, bl;
                wmma::load_matrix_sync(bh, sBh + (n0 + nf * 16) * 40 + k16 * 16, 40);
                wmma::load_matrix_sync(bl, sBl + (n0 + nf * 16) * 40 + k16 * 16, 40);
                #pragma unroll
                for (int mf = 0; mf < 2; mf++) {
                    wmma::mma_sync(acc[mf][nf], ah[mf], bh, acc[mf][nf]);
                    wmma::mma_sync(acc[mf][nf], ah[mf], bl, acc[mf][nf]);
                    wmma::mma_sync(acc[mf][nf], al[mf], bh, acc[mf][nf]);
                }
            }
        }
        __syncthreads();
    }
    #pragma unroll
    for (int mf = 0; mf < 2; mf++)
        #pragma unroll
        for (int nf = 0; nf < 2; nf++)
            wmma::store_matrix_sync(sC + (m0 + mf * 16) * 68 + n0 + nf * 16,
                                    acc[mf][nf], 68, wmma::mem_row_major);
    __syncthreads();
    for (int idx = tid; idx < 128 * 64; idx += 256) {
        int m = idx >> 6, n = idx & 63;
        C[(size_t)(row0 + m) * ldc + ns + n] = sC[m * 68 + n];
    }
}

// ---- fused GRU step: C[64x96] tiles, cp.async double-buffered ----
// grid (B/64=32, H/32=8) = 256 blocks, block 128 (4 warps, 2m x 2n, warp tile 32x48).
// W gate-interleaved rows (k*3+g); block's W rows = ks*3 .. ks*3+96.
__global__ void __launch_bounds__(128) gru_step(
    const __nv_bfloat16* __restrict__ Ah, const __nv_bfloat16* __restrict__ Al,
    const __nv_bfloat16* __restrict__ Wh, const __nv_bfloat16* __restrict__ Wl,
    const float* __restrict__ bih, const float* __restrict__ bhh,
    const float* __restrict__ gi, int t,
    const float* __restrict__ xw, const float* __restrict__ prevp,
    __nv_bfloat16* __restrict__ Oh, __nv_bfloat16* __restrict__ Ol,
    __half* __restrict__ hsout, int mode)
{
    extern __shared__ __align__(16) char smem[];
    // stage layout (bf16 elems): sAh 64*72, sAl 64*72, sWh 96*72, sWl 96*72
    const int A_ELEMS = 64 * 72, W_ELEMS = 96 * 72;
    const int tid  = threadIdx.x;
    const int w    = tid >> 5;
    const int wm   = w & 1, wn = w >> 1;
    const int m0   = wm * 32, n0 = wn * 48;
    const int r0   = blockIdx.x * 64;
    const int ks   = blockIdx.y * 32;
    const int wr0  = ks * 3;

    __nv_bfloat16* stA_h[2]; __nv_bfloat16* stA_l[2];
    __nv_bfloat16* stW_h[2]; __nv_bfloat16* stW_l[2];
    #pragma unroll
    for (int s = 0; s < 2; s++) {
        __nv_bfloat16* base = (__nv_bfloat16*)(smem + (size_t)s * STAGE_BYTES);
        stA_h[s] = base;
        stA_l[s] = base + A_ELEMS;
        stW_h[s] = base + 2 * A_ELEMS;
        stW_l[s] = base + 2 * A_ELEMS + W_ELEMS;
    }

    // async load of chunk kc into stage s
    auto load_chunk = [&](int kc, int s) {
        #pragma unroll 2
        for (int idx = tid; idx < 64 * 8; idx += 128) {
            int m = idx >> 3, v = idx & 7;
            size_t go = (size_t)(r0 + m) * H_ + kc * 64 + v * 8;
            cpa16(stA_h[s] + m * 72 + v * 8, Ah + go);
            cpa16(stA_l[s] + m * 72 + v * 8, Al + go);
        }
        #pragma unroll 2
        for (int idx = tid; idx < 96 * 8; idx += 128) {
            int lr = idx >> 3, v = idx & 7;
            size_t go = (size_t)(wr0 + lr) * H_ + kc * 64 + v * 8;
            cpa16(stW_h[s] + lr * 72 + v * 8, Wh + go);
            cpa16(stW_l[s] + lr * 72 + v * 8, Wl + go);
        }
        asm volatile("cp.async.commit_group;\n");
    };

    wmma::fragment<wmma::accumulator, 16, 16, 16, float> acc[2][3];
    #pragma unroll
    for (int a = 0; a < 2; a++)
        #pragma unroll
        for (int b = 0; b < 3; b++) wmma::fill_fragment(acc[a][b], 0.f);

    load_chunk(0, 0);
    load_chunk(1, 1);

    #pragma unroll
    for (int kc = 0; kc < 4; kc++) {
        if (kc < 3) asm volatile("cp.async.wait_group 1;\n");
        else        asm volatile("cp.async.wait_group 0;\n");
        __syncthreads();
        const int s = kc & 1;
        #pragma unroll
        for (int k16 = 0; k16 < 4; k16++) {
            wmma::fragment<wmma::matrix_a, 16, 16, 16, __nv_bfloat16, wmma::row_major> ah[2], al[2];
            #pragma unroll
            for (int mf = 0; mf < 2; mf++) {
                wmma::load_matrix_sync(ah[mf], stA_h[s] + (m0 + mf * 16) * 72 + k16 * 16, 72);
                wmma::load_matrix_sync(al[mf], stA_l[s] + (m0 + mf * 16) * 72 + k16 * 16, 72);
            }
            #pragma unroll
            for (int nf = 0; nf < 3; nf++) {
                wmma::fragment<wmma::matrix_b, 16, 16, 16, __nv_bfloat16, wmma::col_major> bh, bl;
                wmma::load_matrix_sync(bh, stW_h[s] + (n0 + nf * 16) * 72 + k16 * 16, 72);
                wmma::load_matrix_sync(bl, stW_l[s] + (n0 + nf * 16) * 72 + k16 * 16, 72);
                #pragma unroll
                for (int mf = 0; mf < 2; mf++) {
                    wmma::mma_sync(acc[mf][nf], ah[mf], bh, acc[mf][nf]);
                    wmma::mma_sync(acc[mf][nf], ah[mf], bl, acc[mf][nf]);
                    wmma::mma_sync(acc[mf][nf], al[mf], bh, acc[mf][nf]);
                }
            }
        }
        __syncthreads();                 // all warps done reading stage s
        if (kc + 2 < 4) load_chunk(kc + 2, s);
    }

    // C tile to smem (reuse buffers): 64 x 100 floats = 25.6KB
    float* sC = (float*)smem;
    #pragma unroll
    for (int mf = 0; mf < 2; mf++)
        #pragma unroll
        for (int nf = 0; nf < 3; nf++)
            wmma::store_matrix_sync(sC + (m0 + mf * 16) * 100 + n0 + nf * 16,
                                    acc[mf][nf], 100, wmma::mem_row_major);
    __syncthreads();

    // GRU epilogue: 64 rows x 32 hidden cols, 16 per thread
    #pragma unroll
    for (int e = 0; e < 16; e++) {
        int id = e * 128 + tid;
        int m = id >> 5, kl = id & 31;
        int b = r0 + m;
        int k = ks + kl;
        float ghR = sC[m * 100 + kl * 3 + 0] + bhh[k];
        float ghZ = sC[m * 100 + kl * 3 + 1] + bhh[H_ + k];
        float ghN = sC[m * 100 + kl * 3 + 2] + bhh[2 * H_ + k];
        float giR, giZ, giN;
        if (mode == 0) {
            const float* gp = gi + ((size_t)b * T_ + t) * G3;
            giR = gp[k]          + bih[k];
            giZ = gp[H_ + k]     + bih[H_ + k];
            giN = gp[2 * H_ + k] + bih[2 * H_ + k];
        } else {
            float pv = prevp[b];
            giR = pv * xw[k]          + bih[k];
            giZ = pv * xw[H_ + k]     + bih[H_ + k];
            giN = pv * xw[2 * H_ + k] + bih[2 * H_ + k];
        }
        float r = sigf(giR + ghR);
        float z = sigf(giZ + ghZ);
        float n = tanhf(giN + r * ghN);
        size_t hi = (size_t)b * H_ + k;
        float hold = __bfloat162float(Ah[hi]) + __bfloat162float(Al[hi]);
        float hn = (1.f - z) * n + z * hold;
        __nv_bfloat16 bh_ = __float2bfloat16(hn);
        Oh[hi] = bh_;
        Ol[hi] = __float2bfloat16(hn - __bfloat162float(bh_));
        if (mode == 0) hsout[((size_t)b * T_ + t) * H_ + k] = __float2half(hn);
    }
}

// ---- attention precompute: Asc = Wq.hs, Csc = bq.hs ----
__global__ void attn_pre(const float* __restrict__ Wq, const float* __restrict__ bq)
{
    int warp = threadIdx.x >> 5, lane = threadIdx.x & 31;
    int row = blockIdx.x * 8 + warp;
    const __half* hp = g_hs + (size_t)row * H_;
    float sa = 0.f, sc = 0.f;
    #pragma unroll
    for (int h = lane; h < H_; h += 32) {
        float v = __half2float(hp[h]);
        sa += Wq[h] * v;
        sc += bq[h] * v;
    }
    #pragma unroll
    for (int o = 16; o > 0; o >>= 1) {
        sa += __shfl_down_sync(0xffffffffu, sa, o);
        sc += __shfl_down_sync(0xffffffffu, sc, o);
    }
    if (lane == 0) { g_Asc[row] = sa; g_Csc[row] = sc; }
}

// ---- decoder attention: softmax + ctx (split output). one block per batch ----
__global__ void __launch_bounds__(256) dec_attn(const float* __restrict__ prevsrc)
{
    __shared__ float ssc[128];
    __shared__ float sred[2];
    const int b = blockIdx.x, tid = threadIdx.x;
    float prev = prevsrc[b];

    if (tid < 128)
        ssc[tid] = (prev * g_Asc[b * T_ + tid] + g_Csc[b * T_ + tid]) * 0.0625f;
    __syncthreads();
    if (tid < 32) {
        float m = -1e30f;
        for (int i = tid; i < 128; i += 32) m = fmaxf(m, ssc[i]);
        #pragma unroll
        for (int o = 16; o > 0; o >>= 1) m = fmaxf(m, __shfl_down_sync(0xffffffffu, m, o));
        if (tid == 0) sred[0] = m;
    }
    __syncthreads();
    float mx = sred[0];
    if (tid < 128) ssc[tid] = expf(ssc[tid] - mx);
    __syncthreads();
    if (tid < 32) {
        float sum = 0.f;
        for (int i = tid; i < 128; i += 32) sum += ssc[i];
        #pragma unroll
        for (int o = 16; o > 0; o >>= 1) sum += __shfl_down_sync(0xffffffffu, sum, o);
        if (tid == 0) sred[1] = sum;
    }
    __syncthreads();
    float inv = 1.f / sred[1];
    const __half* hp = g_hs + (size_t)b * T_ * H_ + tid;
    float accv = 0.f;
    #pragma unroll 4
    for (int t2 = 0; t2 < T_; t2++)
        accv += ssc[t2] * __half2float(hp[(size_t)t2 * H_]);
    float v = accv * inv;
    __nv_bfloat16 h = __float2bfloat16(v);
    g_ctxh[b * H_ + tid] = h;
    g_ctxl[b * H_ + tid] = __float2bfloat16(v - __bfloat162float(h));
}

// ---- fused fc1(relu)+fc2: out[:,s] and prev. hd pre-split input ----
__global__ void __launch_bounds__(256) fc_fused(
    const __nv_bfloat16* __restrict__ Wh, const __nv_bfloat16* __restrict__ Wl,
    const float* __restrict__ f1b, const float* __restrict__ f2W,
    const float* __restrict__ f2b,
    float* __restrict__ dout, float* __restrict__ prevout, int s)
{
    __shared__ __align__(16) __nv_bfloat16 sAh[32 * 72], sAl[32 * 72];
    __shared__ __align__(16) __nv_bfloat16 sWh[64 * 72], sWl[64 * 72];
    __shared__ float sC[32 * 68];

    const int tid  = threadIdx.x;
    const int lane = tid & 31;
    const int w    = tid >> 5;
    const int wm   = w & 1, wn = w >> 1;
    const int r0   = blockIdx.x * 32;

    float fsum[4] = {0.f, 0.f, 0.f, 0.f};

    for (int nc = 0; nc < 4; nc++) {
        wmma::fragment<wmma::accumulator, 16, 16, 16, float> acc;
        wmma::fill_fragment(acc, 0.f);
        for (int kc = 0; kc < 4; kc++) {
            for (int idx = tid; idx < 32 * 8; idx += 256) {
                int m = idx >> 3, v = idx & 7;
                size_t go = (size_t)(r0 + m) * H_ + kc * 64 + v * 8;
                *(uint4*)(sAh + m * 72 + v * 8) = *(const uint4*)(g_hdh + go);
                *(uint4*)(sAl + m * 72 + v * 8) = *(const uint4*)(g_hdl + go);
            }
            for (int idx = tid; idx < 64 * 8; idx += 256) {
                int n = idx >> 3, v = idx & 7;
                size_t go = (size_t)(nc * 64 + n) * H_ + kc * 64 + v * 8;
                *(uint4*)(sWh + n * 72 + v * 8) = *(const uint4*)(Wh + go);
                *(uint4*)(sWl + n * 72 + v * 8) = *(const uint4*)(Wl + go);
            }
            __syncthreads();
            #pragma unroll
            for (int k16 = 0; k16 < 4; k16++) {
                wmma::fragment<wmma::matrix_a, 16, 16, 16, __nv_bfloat16, wmma::row_major> ah, al;
                wmma::load_matrix_sync(ah, sAh + (wm * 16) * 72 + k16 * 16, 72);
                wmma::load_matrix_sync(al, sAl + (wm * 16) * 72 + k16 * 16, 72);
                wmma::fragment<wmma::matrix_b, 16, 16, 16, __nv_bfloat16, wmma::col_major> bh, bl;
                wmma::load_matrix_sync(bh, sWh + (wn * 16) * 72 + k16 * 16, 72);
                wmma::load_matrix_sync(bl, sWl + (wn * 16) * 72 + k16 * 16, 72);
                wmma::mma_sync(acc, ah, bh, acc);
                wmma::mma_sync(acc, ah, bl, acc);
                wmma::mma_sync(acc, al, bh, acc);
            }
            __syncthreads();
        }
        wmma::store_matrix_sync(sC + (wm * 16) * 68 + wn * 16, acc, 68, wmma::mem_row_major);
        __syncthreads();
        #pragma unroll
        for (int rr = 0; rr < 4; rr++) {
            int row = w * 4 + rr;
            float a0 = fmaxf(sC[row * 68 + lane]      + f1b[nc * 64 + lane],      0.f) * f2W[nc * 64 + lane];
            float a1 = fmaxf(sC[row * 68 + 32 + lane] + f1b[nc * 64 + 32 + lane], 0.f) * f2W[nc * 64 + 32 + lane];
            float v = a0 + a1;
            #pragma unroll
            for (int o = 16; o > 0; o >>= 1) v += __shfl_down_sync(0xffffffffu, v, o);
            if (lane == 0) fsum[rr] += v;
        }
        __syncthreads();
    }
    if (lane == 0) {
        #pragma unroll
        for (int rr = 0; rr < 4; rr++) {
            int b = r0 + w * 4 + rr;
            float o = fsum[rr] + f2b[0];
            dout[(size_t)b * OL + s] = o;
            prevout[b] = o;
        }
    }
}

// ---- host launch ----
extern "C" void kernel_launch(void* const* d_in, const int* in_sizes, int n_in,
                              void* d_out, int out_size)
{
    const float* x    = (const float*)d_in[0];
    const float* h0   = (const float*)d_in[1];
    const float* eWih = (const float*)d_in[2];
    const float* eWhh = (const float*)d_in[3];
    const float* ebih = (const float*)d_in[4];
    const float* ebhh = (const float*)d_in[5];
    const float* dWih = (const float*)d_in[6];
    const float* dWhh = (const float*)d_in[7];
    const float* dbih = (const float*)d_in[8];
    const float* dbhh = (const float*)d_in[9];
    const float* Wq   = (const float*)d_in[10];
    const float* bq   = (const float*)d_in[11];
    const float* f1W  = (const float*)d_in[12];
    const float* f1b  = (const float*)d_in[13];
    const float* f2W  = (const float*)d_in[14];
    const float* f2b  = (const float*)d_in[15];
    float* out = (float*)d_out;

    cudaFuncSetAttribute(gru_step, cudaFuncAttributeMaxDynamicSharedMemorySize, GRU_SMEM);

    void *p_gi, *p_hhi, *p_hlo, *p_ctxh, *p_ctxl, *p_hdh, *p_hdl, *p_hs, *p_prev0, *p_prev;
    void *p_ihh, *p_ihl, *p_ehh, *p_ehl, *p_dhh, *p_dhl, *p_f1h, *p_f1l;
    cudaGetSymbolAddress(&p_gi, g_gi);
    cudaGetSymbolAddress(&p_hhi, g_hhi);
    cudaGetSymbolAddress(&p_hlo, g_hlo);
    cudaGetSymbolAddress(&p_ctxh, g_ctxh);
    cudaGetSymbolAddress(&p_ctxl, g_ctxl);
    cudaGetSymbolAddress(&p_hdh, g_hdh);
    cudaGetSymbolAddress(&p_hdl, g_hdl);
    cudaGetSymbolAddress(&p_hs, g_hs);
    cudaGetSymbolAddress(&p_prev0, g_prev0);
    cudaGetSymbolAddress(&p_prev, g_prev);
    cudaGetSymbolAddress(&p_ihh, ih_hi); cudaGetSymbolAddress(&p_ihl, ih_lo);
    cudaGetSymbolAddress(&p_ehh, eh_hi); cudaGetSymbolAddress(&p_ehl, eh_lo);
    cudaGetSymbolAddress(&p_dhh, dh_hi); cudaGetSymbolAddress(&p_dhl, dh_lo);
    cudaGetSymbolAddress(&p_f1h, f1_hi); cudaGetSymbolAddress(&p_f1l, f1_lo);

    prep_weights<<<(G3 * F_ + 2 * G3 * H_ + FCH * H_ + 255) / 256, 256>>>(eWih, eWhh, dWhh, f1W);
    prep_state<<<(B_ * H_ + 255) / 256, 256>>>(x, h0);

    // gi = X @ Wih^T (X viewed as [B*T, F])
    gemm_split<<<dim3(B_ * T_ / 128, G3 / 64), 256>>>(
        x, F_, (__nv_bfloat16*)p_ihh, (__nv_bfloat16*)p_ihl,
        (float*)p_gi, G3, F_);

    // encoder recurrence
    int pin = 0;
    for (int t = 0; t < T_; t++) {
        gru_step<<<dim3(B_ / 64, H_ / 32), 128, GRU_SMEM>>>(
            (__nv_bfloat16*)p_hhi + (size_t)pin * B_ * H_,
            (__nv_bfloat16*)p_hlo + (size_t)pin * B_ * H_,
            (__nv_bfloat16*)p_ehh, (__nv_bfloat16*)p_ehl,
            ebih, ebhh,
            (const float*)p_gi, t,
            nullptr, nullptr,
            (__nv_bfloat16*)p_hhi + (size_t)(pin ^ 1) * B_ * H_,
            (__nv_bfloat16*)p_hlo + (size_t)(pin ^ 1) * B_ * H_,
            (__half*)p_hs, 0);
        pin ^= 1;
    }

    attn_pre<<<B_ * T_ / 8, 256>>>(Wq, bq);

    // decoder: 32 steps of (attention+ctx) -> (gru) -> (fc1+fc2)
    for (int s = 0; s < OL; s++) {
        const float* prevsrc = (s == 0) ? (const float*)p_prev0 : (const float*)p_prev;
        dec_attn<<<B_, 256>>>(prevsrc);
        gru_step<<<dim3(B_ / 64, H_ / 32), 128, GRU_SMEM>>>(
            (__nv_bfloat16*)p_ctxh, (__nv_bfloat16*)p_ctxl,
            (__nv_bfloat16*)p_dhh, (__nv_bfloat16*)p_dhl,
            dbih, dbhh,
            nullptr, 0,
            dWih, prevsrc,
            (__nv_bfloat16*)p_hdh, (__nv_bfloat16*)p_hdl,
            nullptr, 1);
        fc_fused<<<B_ / 32, 256>>>(
            (__nv_bfloat16*)p_f1h, (__nv_bfloat16*)p_f1l,
            f1b, f2W, f2b,
            out, (float*)p_prev, s);
    }
}